// round 17
// baseline (speedup 1.0000x reference)
#include <cuda_runtime.h>
#include <cuda_bf16.h>
#include <cstdint>

// Problem constants (B=32, C=1 heat, H=W=256, K=500)
#define NB     32
#define WID    256
#define HW     65536
#define KTOP   500
#define NIMG   64
#define SURV   1024        // survivor cap / sort width
#define BINS   4096        // value bins (fallback only)
#define TPB    256

#define TAU_P  0.988f      // pred threshold: cnt E~786 in [500,1024] (8.5/10 sigma);
                           // post-NMS valid E~720 >= 500 (rank-500 ~0.99212)
#define TAU_G  0.9896f     // gt threshold: cnt E~682 in [500,1024] (13/7 sigma)

#define GSL    8                    // slices per image
#define SCAN_BLOCKS (NIMG * GSL)    // 512 (img = blk>>3; imgs 0-31 pred, 32-63 gt)
#define SLPX4  (HW / 4 / GSL)       // 2048 float4 per slice
#define SC_ITER (SLPX4 / TPB)       // 8 float4 per thread

// Scratch (static device globals — zero-init; consumers reset what they use)
__device__ unsigned long long g_cand[NB][SURV];     // pred pixels >= TAU_P
__device__ int      g_cnt[NB];
__device__ unsigned long long g_gtkeys[NB][SURV];   // gt pixels >= TAU_G
__device__ int      g_gtcnt[NB];
__device__ int      g_img_ticket[NIMG];             // slice-completion tickets
__device__ float    g_xs[NIMG][KTOP];
__device__ float    g_ys[NIMG][KTOP];
__device__ double   g_sum;
__device__ int      g_tot;
__device__ unsigned g_ticket;

// per-coordinate assembly tables (see reference _assemble)
__constant__ int   c_whA[10] = {-1,-1, 0, 1, 2, 3, 4, 5, 6, 7};   // m==1
__constant__ int   c_whB[10] = {-1,-1,-1, 9, 8,-1,-1, 9, 8,-1};   // m==0
__constant__ float c_sgn[10] = {0,0,0,-0.5f,0.5f,0,0,0.5f,-0.5f,0};

__device__ __forceinline__ int val_bin(float v) {
    int b = (int)(v * 4096.0f);
    if (b < 0) b = 0;
    if (b > BINS - 1) b = BINS - 1;
    return b;
}
__device__ __forceinline__ unsigned long long uomin(unsigned long long a, unsigned long long b) { return a < b ? a : b; }
__device__ __forceinline__ unsigned long long uomax(unsigned long long a, unsigned long long b) { return a > b ? a : b; }

// key = (~fbits << 32) | idx  => ascending 64-bit sort == lax.top_k order
// (value desc, index asc).
__device__ __forceinline__ unsigned long long mkkey(float v, unsigned idx) {
    return ((unsigned long long)(~__float_as_uint(v)) << 32) | idx;
}

// NMS test from gmem (L2-resident heatmap). Keep iff v>0 and no 3x3 neighbor
// exceeds v (ties kept) — exactly hmax==heat semantics.
__device__ __forceinline__ bool nms_ok_g(const float* hm, int y, int x, float v) {
    if (v <= 0.f) return false;
    #pragma unroll
    for (int dy = -1; dy <= 1; dy++) {
        int ny = y + dy;
        if (ny < 0 || ny >= WID) continue;
        #pragma unroll
        for (int dx = -1; dx <= 1; dx++) {
            if (dy == 0 && dx == 0) continue;
            int nx = x + dx;
            if (nx < 0 || nx >= WID) continue;
            if (__ldg(&hm[ny * WID + nx]) > v) return false;
        }
    }
    return true;
}

// bitonic sort ascending over 1024 smem keys with 256 threads (4 elems/thread).
__device__ __forceinline__ void bitonic1024_t256(unsigned long long* keys, int tid) {
    for (unsigned kk = 2; kk <= SURV; kk <<= 1) {
        for (unsigned j = kk >> 1; j > 0; j >>= 1) {
            #pragma unroll
            for (int rep = 0; rep < 4; rep++) {
                unsigned i = tid + rep * TPB;
                unsigned ixj = i ^ j;
                if (ixj > i) {
                    unsigned long long a = keys[i], b = keys[ixj];
                    bool up = ((i & kk) == 0);
                    if ((a > b) == up) { keys[i] = b; keys[ixj] = a; }
                }
            }
            __syncthreads();
        }
    }
}

// suffix-scan over 4096 smem bins with 256 threads (fallback only): smallest
// bin with suffix-count >= KTOP.
__device__ __forceinline__ int compute_bstar_t256(const int* hist, int* psum,
                                                  int* wsuf, int* s_bstar, int tid) {
    int lane = tid & 31, warp = tid >> 5;     // 8 warps
    int gv = 0;
    #pragma unroll
    for (int b = 0; b < 16; b++) gv += hist[16 * tid + b];
    int v = gv;
    #pragma unroll
    for (int off = 1; off < 32; off <<= 1) {
        int t2 = __shfl_down_sync(0xffffffffu, v, off);
        if (lane + off < 32) v += t2;
    }
    if (lane == 0) wsuf[warp] = v;
    __syncthreads();
    if (warp == 0 && lane < 8) {
        int t = wsuf[lane];
        #pragma unroll
        for (int off = 1; off < 8; off <<= 1) {
            int t2 = __shfl_down_sync(0x000000ffu, t, off);
            if (lane + off < 8) t += t2;
        }
        wsuf[lane] = t;
    }
    __syncthreads();
    int suffix = v + ((warp < 7) ? wsuf[warp + 1] : 0);   // inclusive over groups
    psum[tid] = suffix;
    __syncthreads();
    int above = (tid < TPB - 1) ? psum[tid + 1] : 0;
    if (suffix >= KTOP && above < KTOP) {
        int c = above;
        int bstar = 16 * tid;
        for (int b = 16 * tid + 15; b >= 16 * tid; --b) {
            c += hist[b];
            if (c >= KTOP) { bstar = b; break; }
        }
        *s_bstar = bstar;
    }
    __syncthreads();
    return *s_bstar;
}

// ---------------------------------------------------------------------------
// FUSED SCAN+SORT kernel (512 blocks x 256 threads; 8 slice-blocks per image).
// Phase 1 (all blocks): threshold-collect the block's slice into the image's
//   global survivor list (8 independent float4 loads, one "any" ballot/float4,
//   warp-aggregated append). Pred uses TAU_P, gt uses TAU_G. No NMS yet.
// Phase 2 (last-arriving block per image, via __threadfence + ticket): load
//   survivors (volatile: bypass L1 for cross-CTA coherence), pred: 3x3 NMS
//   check vs the L2-hot heatmap, bitonic sort, emit ranks 0..499.
// Exactness: pred fast path requires cnt in [500,1024] AND >=500 NMS-valid:
//   then every NMS survivor with value >= rank-500 is >= TAU_P and hence in
//   the list. GT fast path requires cnt in [500,1024] (reference top_k's the
//   RAW gt heatmap). Otherwise: exact histogram+prune fallback (never taken
//   statistically, guards correctness for any input).
__global__ void __launch_bounds__(TPB) k_scan_sort(const float* __restrict__ pred_hm,
                                                   const float* __restrict__ gt_hm) {
    __shared__ unsigned long long keys[SURV];   // 8 KB
    __shared__ int hist[BINS];                  // 16 KB (fallback only)
    __shared__ int psum[TPB];
    __shared__ int wsuf[8];
    __shared__ int s_bstar, s_nvalid, s_nsurv, s_last;

    int blk = blockIdx.x;
    int img = blk >> 3;                   // 0..63
    int sl  = blk & (GSL - 1);
    bool is_gt = (img >= NB);
    int b = is_gt ? (img - NB) : img;
    const float* hm = (is_gt ? gt_hm : pred_hm) + (size_t)b * HW;
    float tau = is_gt ? TAU_G : TAU_P;
    int* cntp = is_gt ? &g_gtcnt[b] : &g_cnt[b];
    unsigned long long* buf = is_gt ? g_gtkeys[b] : g_cand[b];

    int tid = threadIdx.x;
    int lane = tid & 31;

    // ---- phase 1: threshold-collect this slice ----
    {
        const float4* hm4 = reinterpret_cast<const float4*>(hm) + sl * SLPX4;
        int pix0 = sl * SLPX4 * 4;
        float4 v[SC_ITER];
        #pragma unroll
        for (int it = 0; it < SC_ITER; it++)      // 8 independent loads (MLP=8)
            v[it] = __ldg(&hm4[it * TPB + tid]);
        #pragma unroll
        for (int it = 0; it < SC_ITER; it++) {
            float vv[4] = {v[it].x, v[it].y, v[it].z, v[it].w};
            bool any = (vv[0] >= tau) | (vv[1] >= tau) | (vv[2] >= tau) | (vv[3] >= tau);
            if (__ballot_sync(0xffffffffu, any)) {
                int base_pix = pix0 + (it * TPB + tid) * 4;
                #pragma unroll
                for (int comp = 0; comp < 4; comp++) {
                    bool keep = (vv[comp] >= tau);
                    unsigned ballot = __ballot_sync(0xffffffffu, keep);
                    if (keep) {
                        int leader = __ffs(ballot) - 1;
                        int base = 0;
                        if (lane == leader) base = atomicAdd(cntp, __popc(ballot));
                        base = __shfl_sync(ballot, base, leader);
                        int slot = base + __popc(ballot & ((1u << lane) - 1u));
                        if (slot < SURV)
                            buf[slot] = mkkey(vv[comp], (unsigned)(base_pix + comp));
                    }
                }
            }
        }
    }

    // ---- ticket: last block of this image proceeds to sort ----
    __threadfence();
    __syncthreads();
    if (tid == 0) {
        int t = atomicAdd(&g_img_ticket[img], 1);
        s_last = (t == GSL - 1);
    }
    __syncthreads();
    if (!s_last) return;

    // ---- phase 2: sort this image ----
    int cnt = *(volatile int*)cntp;
    bool fast = (cnt >= KTOP && cnt <= SURV);
    if (tid == 0) { s_nvalid = 0; s_nsurv = 0; s_bstar = 0; }
    __syncthreads();

    if (fast) {
        int local_valid = 0;
        #pragma unroll
        for (int rep = 0; rep < 4; rep++) {
            int i = tid + rep * TPB;
            unsigned long long key = 0xFFFFFFFFFFFFFFFFULL;
            if (i < cnt) {
                key = *(volatile unsigned long long*)&buf[i];
                bool valid = true;
                if (!is_gt) {
                    unsigned idx = (unsigned)(key & 0xFFFFFFFFULL);
                    float v = __uint_as_float(~(unsigned)(key >> 32));
                    valid = nms_ok_g(hm, (int)(idx >> 8), (int)(idx & (WID - 1)), v);
                }
                if (!valid) key = 0xFFFFFFFFFFFFFFFFULL;
                else local_valid++;
            }
            keys[i] = key;
        }
        if (local_valid) atomicAdd(&s_nvalid, local_valid);
        __syncthreads();
        fast = (s_nvalid >= KTOP);
    }

    if (!fast) {
        // ---- exact fallback: histogram + prune over the whole heatmap ----
        for (int i = tid; i < BINS; i += TPB) hist[i] = 0;
        __syncthreads();
        for (int i = tid; i < HW; i += TPB) {
            float v = __ldg(&hm[i]);
            bool ok = is_gt ? true : nms_ok_g(hm, i >> 8, i & (WID - 1), v);
            if (ok) atomicAdd(&hist[val_bin(v)], 1);
        }
        __syncthreads();
        int bstar = compute_bstar_t256(hist, psum, wsuf, &s_bstar, tid);
        for (int i = tid; i < HW; i += TPB) {
            float v = __ldg(&hm[i]);
            bool ok = (val_bin(v) >= bstar)
                   && (is_gt ? true : nms_ok_g(hm, i >> 8, i & (WID - 1), v));
            unsigned ballot = __ballot_sync(0xffffffffu, ok);
            if (ok) {
                int leader = __ffs(ballot) - 1;
                int base2 = 0;
                if (lane == leader) base2 = atomicAdd(&s_nsurv, __popc(ballot));
                base2 = __shfl_sync(ballot, base2, leader);
                int slot = base2 + __popc(ballot & ((1u << lane) - 1u));
                if (slot < SURV) keys[slot] = mkkey(v, (unsigned)i);
            }
        }
        __syncthreads();
        int ns = s_nsurv; if (ns > SURV) ns = SURV;
        #pragma unroll
        for (int rep = 0; rep < 4; rep++) {
            int i = tid + rep * TPB;
            if (i >= ns) keys[i] = 0xFFFFFFFFFFFFFFFFULL;
        }
        __syncthreads();
    }

    bitonic1024_t256(keys, tid);

    #pragma unroll
    for (int i = tid; i < KTOP; i += TPB) {
        unsigned p = (unsigned)(keys[i] & 0xFFFFFFFFULL);
        g_xs[img][i] = (float)(p & (WID - 1));
        g_ys[img][i] = (float)(p >> 8);
    }
    // reset consumed state for next graph replay
    if (tid == 0) { g_img_ticket[img] = 0; *cntp = 0; }
}

// ---------------------------------------------------------------------------
// Loss (R8 version, measured best): one thread per (item, coordinate);
// mask gates the gathers.
#define LOSS_TPB 1024
#define LOSS_N   (NB * KTOP * 10)
__global__ void __launch_bounds__(LOSS_TPB)
k_loss(const float* __restrict__ pred_wh, const float* __restrict__ pred_reg,
       const float* __restrict__ pred_cls,
       const float* __restrict__ gt_wh, const float* __restrict__ gt_reg,
       const float* __restrict__ gt_cls,
       const int* __restrict__ gt_ind, const int* __restrict__ gt_mask,
       float* __restrict__ out) {
    int gidx = blockIdx.x * LOSS_TPB + threadIdx.x;
    float lsum = 0.f;
    int lcnt = 0;
    if (gidx < LOSS_N) {
        int t = gidx / 10;
        int c = gidx - t * 10;
        if (__ldg(&gt_mask[t]) != 0) {
            lcnt = 1;
            int b = t / KTOP;
            int k = t - b * KTOP;
            int ind = __ldg(&gt_ind[t]);
            bool odd = (c & 1);
            int iA = c_whA[c], iB = c_whB[c];
            float sg = c_sgn[c];
            float base, gbase;
            if (odd) {
                base  = g_ys[b][k]      + __ldg(&pred_reg[(size_t)(b * 2 + 1) * HW + ind]);
                gbase = g_ys[NB + b][k] + __ldg(&gt_reg[2 * t + 1]);
            } else {
                base  = g_xs[b][k]      + __ldg(&pred_reg[(size_t)(b * 2) * HW + ind]);
                gbase = g_xs[NB + b][k] + __ldg(&gt_reg[2 * t]);
            }
            bool m  = __ldg(&pred_cls[(size_t)b * HW + ind]) > 0.8f;
            bool gm = __ldg(&gt_cls[t]) > 0.8f;
            float pp = base, tt = gbase;
            // m exactly 0/1 in reference => branch == blend bit-exactly
            if (m) { if (iA >= 0) pp += __ldg(&pred_wh[((size_t)b * 10 + iA) * HW + ind]); }
            else   { if (iB >= 0) pp += sg * __ldg(&pred_wh[((size_t)b * 10 + iB) * HW + ind]); }
            if (gm) { if (iA >= 0) tt += __ldg(&gt_wh[10 * t + iA]); }
            else    { if (iB >= 0) tt += sg * __ldg(&gt_wh[10 * t + iB]); }
            float d = fabsf(pp - tt);
            lsum = (d < 1.f) ? 0.5f * d * d : (d - 0.5f);
        }
    }
    #pragma unroll
    for (int off = 16; off > 0; off >>= 1) {
        lsum += __shfl_down_sync(0xffffffffu, lsum, off);
        lcnt += __shfl_down_sync(0xffffffffu, lcnt, off);
    }
    __shared__ float wsum[LOSS_TPB / 32];
    __shared__ int   wcnt[LOSS_TPB / 32];
    int warp = threadIdx.x >> 5, lane = threadIdx.x & 31;
    if (lane == 0) { wsum[warp] = lsum; wcnt[warp] = lcnt; }
    __syncthreads();
    if (warp == 0) {
        float s = (lane < LOSS_TPB / 32) ? wsum[lane] : 0.f;
        int   cc = (lane < LOSS_TPB / 32) ? wcnt[lane] : 0;
        #pragma unroll
        for (int off = 16; off > 0; off >>= 1) {
            s  += __shfl_down_sync(0xffffffffu, s, off);
            cc += __shfl_down_sync(0xffffffffu, cc, off);
        }
        if (lane == 0) {
            atomicAdd(&g_sum, (double)s);
            atomicAdd(&g_tot, cc);
            __threadfence();
            unsigned ticket = atomicAdd(&g_ticket, 1u);
            if (ticket == gridDim.x - 1) {   // last block: finalize + reset
                double fs = g_sum;
                int tot = g_tot;
                float loss = 0.f;
                if (tot > 0) loss = (float)(fs / (double)(tot < 1 ? 1 : tot));
                out[0] = loss;
                g_sum = 0.0; g_tot = 0; g_ticket = 0u;
            }
        }
    }
}

// ---------------------------------------------------------------------------
extern "C" void kernel_launch(void* const* d_in, const int* in_sizes, int n_in,
                              void* d_out, int out_size) {
    const float* pred_hm  = (const float*)d_in[0];
    const float* pred_wh  = (const float*)d_in[1];
    const float* pred_reg = (const float*)d_in[2];
    const float* pred_cls = (const float*)d_in[3];
    const float* gt_hm    = (const float*)d_in[4];
    const float* gt_wh    = (const float*)d_in[5];
    const float* gt_reg   = (const float*)d_in[6];
    const float* gt_cls   = (const float*)d_in[7];
    const int*   gt_ind   = (const int*)d_in[8];
    const int*   gt_mask  = (const int*)d_in[9];
    float* out = (float*)d_out;

    k_scan_sort<<<SCAN_BLOCKS, TPB>>>(pred_hm, gt_hm);
    k_loss<<<(LOSS_N + LOSS_TPB - 1) / LOSS_TPB, LOSS_TPB>>>(
        pred_wh, pred_reg, pred_cls, gt_wh, gt_reg, gt_cls, gt_ind, gt_mask, out);
}